// round 1
// baseline (speedup 1.0000x reference)
#include <cuda_runtime.h>
#include <cuda_fp16.h>
#include <cstdint>
#include <cmath>

// Problem constants
#define NB 64          // batch
#define NS 16          // steps
#define NO 31          // opcodes
#define ND 1024        // hidden dim
#define KTOT (NO*ND)   // 31744  GEMM reduction dim
#define KSPLIT 16
#define KCH (KTOT/KSPLIT)  // 1984
#define BK 32
#define NIT (KCH/BK)       // 62
#define BN 128
#define NTILES (ND/BN)     // 8

// ---------------- device scratch (static globals: allocation-free) ----------------
__device__ __half  g_Kh[(size_t)KTOT * ND];        // 65 MB fp16 kernels, [kk][k]
__device__ __half  g_A[(size_t)NB * KTOT];         // 4 MB  A[b][o*1024+d] = w*h
__device__ float   g_partial[KSPLIT * NB * ND];    // 4 MB  split-K partials
__device__ float   g_h[NB * ND];                   // fp32 hidden state
__device__ float   g_w[NS][NB][NO];                // softmax weights per step
__device__ float   g_gate[NS][NB];                 // sigmoid gates per step

// ---------------- helpers ----------------
__device__ __forceinline__ uint32_t smem_u32(const void* p) {
    return (uint32_t)__cvta_generic_to_shared(p);
}
__device__ __forceinline__ void cp_async16(uint32_t dst, const void* src) {
    asm volatile("cp.async.cg.shared.global [%0], [%1], 16;\n" :: "r"(dst), "l"(src));
}
__device__ __forceinline__ void cp_commit() {
    asm volatile("cp.async.commit_group;\n");
}
__device__ __forceinline__ void cp_wait1() {
    asm volatile("cp.async.wait_group 1;\n");
}
__device__ __forceinline__ void cp_wait0() {
    asm volatile("cp.async.wait_group 0;\n");
}
__device__ __forceinline__ void ldm_x4(uint32_t* r, uint32_t addr) {
    asm volatile("ldmatrix.sync.aligned.m8n8.x4.shared.b16 {%0,%1,%2,%3}, [%4];\n"
                 : "=r"(r[0]), "=r"(r[1]), "=r"(r[2]), "=r"(r[3]) : "r"(addr));
}
__device__ __forceinline__ void ldm_x4t(uint32_t* r, uint32_t addr) {
    asm volatile("ldmatrix.sync.aligned.m8n8.x4.trans.shared.b16 {%0,%1,%2,%3}, [%4];\n"
                 : "=r"(r[0]), "=r"(r[1]), "=r"(r[2]), "=r"(r[3]) : "r"(addr));
}
__device__ __forceinline__ void mma16816(float* c, const uint32_t* a, uint32_t b0, uint32_t b1) {
    asm volatile(
        "mma.sync.aligned.m16n8k16.row.col.f32.f16.f16.f32 "
        "{%0,%1,%2,%3}, {%4,%5,%6,%7}, {%8,%9}, {%0,%1,%2,%3};\n"
        : "+f"(c[0]), "+f"(c[1]), "+f"(c[2]), "+f"(c[3])
        : "r"(a[0]), "r"(a[1]), "r"(a[2]), "r"(a[3]), "r"(b0), "r"(b1));
}

// ---------------- prep: softmax weights + gates ----------------
__global__ void prep_kernel(const float* __restrict__ logits,
                            const float* __restrict__ operands) {
    int bs = blockIdx.x;          // b*NS + s
    int b = bs >> 4, s = bs & 15;
    int lane = threadIdx.x;
    float v = (lane < NO) ? logits[bs * NO + lane] : -INFINITY;
    float m = v;
    #pragma unroll
    for (int off = 16; off > 0; off >>= 1)
        m = fmaxf(m, __shfl_xor_sync(0xffffffffu, m, off));
    float e = (lane < NO) ? expf(v - m) : 0.0f;
    float sum = e;
    #pragma unroll
    for (int off = 16; off > 0; off >>= 1)
        sum += __shfl_xor_sync(0xffffffffu, sum, off);
    if (lane < NO) g_w[s][b][lane] = e / sum;
    if (lane == 0) g_gate[s][b] = 1.0f / (1.0f + expf(-operands[bs * 4 + 3]));
}

// ---------------- convert op_kernels fp32 -> fp16 ----------------
__global__ void convert_kernel(const float* __restrict__ K) {
    size_t i = ((size_t)blockIdx.x * blockDim.x + threadIdx.x) * 8;
    float4 f0 = *(const float4*)(K + i);
    float4 f1 = *(const float4*)(K + i + 4);
    __half2* dst = (__half2*)(g_Kh + i);
    dst[0] = __floats2half2_rn(f0.x, f0.y);
    dst[1] = __floats2half2_rn(f0.z, f0.w);
    dst[2] = __floats2half2_rn(f1.x, f1.y);
    dst[3] = __floats2half2_rn(f1.z, f1.w);
}

// ---------------- GEMM: transformed = A @ Kh  (split-K into g_partial) ----------------
// grid (NTILES, KSPLIT), 256 threads. M=64, N=128 per CTA, K-chunk 1984.
__global__ __launch_bounds__(256, 1) void gemm_step_kernel() {
    const int ntile = blockIdx.x;
    const int ks = blockIdx.y;
    const int tid = threadIdx.x;
    const int wid = tid >> 5, lane = tid & 31;
    const int wm = wid & 1, wn = wid >> 1;   // 2 x 4 warp grid, 32x32 per warp

    __shared__ __half As[2][64 * 40];   // 32 used cols, stride 40 (conflict-free)
    __shared__ __half Bs[2][32 * 136];  // 128 used cols, stride 136 (conflict-free)

    float c[2][4][4];
    #pragma unroll
    for (int i = 0; i < 2; i++)
        #pragma unroll
        for (int j = 0; j < 4; j++)
            #pragma unroll
            for (int q = 0; q < 4; q++) c[i][j][q] = 0.0f;

    const int k0 = ks * KCH;
    const int nbase = ntile * BN;

    // tile loaders
    const int arow = tid >> 2, ach = tid & 3;          // A: 64 rows x 4 chunks
    const int brow = tid >> 4, bch = tid & 15;         // B: 16 rows x 16 chunks (x2)

    #define LOAD_TILES(buf, kg) do {                                            \
        cp_async16(smem_u32(&As[buf][arow * 40 + ach * 8]),                     \
                   g_A + (size_t)arow * KTOT + (kg) + ach * 8);                 \
        cp_async16(smem_u32(&Bs[buf][brow * 136 + bch * 8]),                    \
                   g_Kh + (size_t)((kg) + brow) * ND + nbase + bch * 8);        \
        cp_async16(smem_u32(&Bs[buf][(brow + 16) * 136 + bch * 8]),             \
                   g_Kh + (size_t)((kg) + brow + 16) * ND + nbase + bch * 8);   \
    } while (0)

    LOAD_TILES(0, k0);
    cp_commit();

    for (int it = 0; it < NIT; ++it) {
        const int buf = it & 1;
        if (it + 1 < NIT) {
            LOAD_TILES(buf ^ 1, k0 + (it + 1) * BK);
            cp_commit();
            cp_wait1();
        } else {
            cp_wait0();
        }
        __syncthreads();

        #pragma unroll
        for (int kh = 0; kh < 2; ++kh) {
            uint32_t a[2][4];
            #pragma unroll
            for (int mf = 0; mf < 2; ++mf) {
                uint32_t addr = smem_u32(
                    &As[buf][(wm * 32 + mf * 16 + (lane & 15)) * 40 + kh * 16 + (lane >> 4) * 8]);
                ldm_x4(a[mf], addr);
            }
            uint32_t bb[2][4];
            #pragma unroll
            for (int np = 0; np < 2; ++np) {
                uint32_t addr = smem_u32(
                    &Bs[buf][(kh * 16 + (lane & 15)) * 136 + wn * 32 + np * 16 + (lane >> 4) * 8]);
                ldm_x4t(bb[np], addr);
            }
            #pragma unroll
            for (int mf = 0; mf < 2; ++mf)
                #pragma unroll
                for (int nf = 0; nf < 4; ++nf)
                    mma16816(c[mf][nf], a[mf], bb[nf >> 1][(nf & 1) * 2], bb[nf >> 1][(nf & 1) * 2 + 1]);
        }
        __syncthreads();
    }

    // epilogue: write this split's partial
    float* pp = g_partial + ((size_t)ks * NB * ND);
    #pragma unroll
    for (int mf = 0; mf < 2; ++mf) {
        #pragma unroll
        for (int nf = 0; nf < 4; ++nf) {
            int m = wm * 32 + mf * 16 + (lane >> 2);
            int n = nbase + wn * 32 + nf * 8 + (lane & 3) * 2;
            pp[(size_t)m * ND + n]           = c[mf][nf][0];
            pp[(size_t)m * ND + n + 1]       = c[mf][nf][1];
            pp[(size_t)(m + 8) * ND + n]     = c[mf][nf][2];
            pp[(size_t)(m + 8) * ND + n + 1] = c[mf][nf][3];
        }
    }
}

// ---------------- update: reduce partials, gate, build next A ----------------
// t = -1: init (h = signal, build A for step 0).  t = 15: final (write d_out).
__global__ void update_kernel(const float* __restrict__ signal,
                              float* __restrict__ out, int t) {
    const int b = blockIdx.x;
    const int d = threadIdx.x;
    const bool last = (t == NS - 1);

    __shared__ float wsh[NO];
    if (!last && d < NO) wsh[d] = g_w[t + 1][b][d];

    float hn;
    if (t < 0) {
        hn = signal[b * ND + d];
    } else {
        float tr = 0.0f;
        #pragma unroll
        for (int ks = 0; ks < KSPLIT; ++ks)
            tr += g_partial[(size_t)ks * NB * ND + b * ND + d];
        float g = g_gate[t][b];
        float h = g_h[b * ND + d];
        hn = g * tr + (1.0f - g) * h;
    }
    __syncthreads();

    if (last) {
        out[b * ND + d] = hn;
    } else {
        g_h[b * ND + d] = hn;
        #pragma unroll
        for (int o = 0; o < NO; ++o)
            g_A[(size_t)b * KTOT + o * ND + d] = __float2half(wsh[o] * hn);
    }
}

// ---------------- launch ----------------
extern "C" void kernel_launch(void* const* d_in, const int* in_sizes, int n_in,
                              void* d_out, int out_size) {
    const float* logits   = (const float*)d_in[0];  // (64,16,31)
    const float* operands = (const float*)d_in[1];  // (64,16,4)
    const float* signal   = (const float*)d_in[2];  // (64,1024)
    const float* opk      = (const float*)d_in[3];  // (31,1024,1024)
    float* out = (float*)d_out;                     // (64,1024)

    prep_kernel<<<NB * NS, 32>>>(logits, operands);
    convert_kernel<<<(KTOT * ND) / 8 / 256, 256>>>(opk);
    update_kernel<<<NB, ND>>>(signal, out, -1);   // init h + A for step 0

    for (int t = 0; t < NS; ++t) {
        gemm_step_kernel<<<dim3(NTILES, KSPLIT), 256>>>();
        update_kernel<<<NB, ND>>>(signal, out, t);
    }
}

// round 2
// speedup vs baseline: 1.0985x; 1.0985x over previous
#include <cuda_runtime.h>
#include <cuda_fp16.h>
#include <cstdint>
#include <cmath>

// Problem constants
#define NB 64          // batch
#define NS 16          // steps
#define NO 31          // opcodes
#define ND 1024        // hidden dim
#define KTOT (NO*ND)   // 31744  GEMM reduction dim
#define KSPLIT 32
#define KCH (KTOT/KSPLIT)  // 992
#define BK 32
#define NIT (KCH/BK)       // 31
#define BN 128
#define NTILES (ND/BN)     // 8
#define STAGES 3

// ---------------- device scratch (static globals: allocation-free) ----------------
__device__ __half  g_Kh[(size_t)KTOT * ND];        // 65 MB fp16 kernels, [kk][k]
__device__ __half  g_A[(size_t)NB * KTOT];         // 4 MB  A[b][o*1024+d] = w*h
__device__ float   g_partial[KSPLIT * NB * ND];    // 8 MB  split-K partials
__device__ float   g_h[NB * ND];                   // fp32 hidden state
__device__ float   g_w[NS][NB][NO];                // softmax weights per step
__device__ float   g_gate[NS][NB];                 // sigmoid gates per step

// ---------------- helpers ----------------
__device__ __forceinline__ uint32_t smem_u32(const void* p) {
    return (uint32_t)__cvta_generic_to_shared(p);
}
__device__ __forceinline__ void cp_async16(uint32_t dst, const void* src) {
    asm volatile("cp.async.cg.shared.global [%0], [%1], 16;\n" :: "r"(dst), "l"(src));
}
__device__ __forceinline__ void cp_commit() {
    asm volatile("cp.async.commit_group;\n");
}
__device__ __forceinline__ void cp_wait1() {
    asm volatile("cp.async.wait_group 1;\n");
}
__device__ __forceinline__ void ldm_x4(uint32_t* r, uint32_t addr) {
    asm volatile("ldmatrix.sync.aligned.m8n8.x4.shared.b16 {%0,%1,%2,%3}, [%4];\n"
                 : "=r"(r[0]), "=r"(r[1]), "=r"(r[2]), "=r"(r[3]) : "r"(addr));
}
__device__ __forceinline__ void ldm_x4t(uint32_t* r, uint32_t addr) {
    asm volatile("ldmatrix.sync.aligned.m8n8.x4.trans.shared.b16 {%0,%1,%2,%3}, [%4];\n"
                 : "=r"(r[0]), "=r"(r[1]), "=r"(r[2]), "=r"(r[3]) : "r"(addr));
}
__device__ __forceinline__ void mma16816(float* c, const uint32_t* a, uint32_t b0, uint32_t b1) {
    asm volatile(
        "mma.sync.aligned.m16n8k16.row.col.f32.f16.f16.f32 "
        "{%0,%1,%2,%3}, {%4,%5,%6,%7}, {%8,%9}, {%0,%1,%2,%3};\n"
        : "+f"(c[0]), "+f"(c[1]), "+f"(c[2]), "+f"(c[3])
        : "r"(a[0]), "r"(a[1]), "r"(a[2]), "r"(a[3]), "r"(b0), "r"(b1));
}

// ---------------- prep: softmax weights + gates ----------------
__global__ void prep_kernel(const float* __restrict__ logits,
                            const float* __restrict__ operands) {
    int bs = blockIdx.x;          // b*NS + s
    int b = bs >> 4, s = bs & 15;
    int lane = threadIdx.x;
    float v = (lane < NO) ? logits[bs * NO + lane] : -INFINITY;
    float m = v;
    #pragma unroll
    for (int off = 16; off > 0; off >>= 1)
        m = fmaxf(m, __shfl_xor_sync(0xffffffffu, m, off));
    float e = (lane < NO) ? expf(v - m) : 0.0f;
    float sum = e;
    #pragma unroll
    for (int off = 16; off > 0; off >>= 1)
        sum += __shfl_xor_sync(0xffffffffu, sum, off);
    if (lane < NO) g_w[s][b][lane] = e / sum;
    if (lane == 0) g_gate[s][b] = 1.0f / (1.0f + expf(-operands[bs * 4 + 3]));
}

// ---------------- convert op_kernels fp32 -> fp16 ----------------
__global__ void convert_kernel(const float* __restrict__ K) {
    size_t i = ((size_t)blockIdx.x * blockDim.x + threadIdx.x) * 8;
    float4 f0 = *(const float4*)(K + i);
    float4 f1 = *(const float4*)(K + i + 4);
    __half2* dst = (__half2*)(g_Kh + i);
    dst[0] = __floats2half2_rn(f0.x, f0.y);
    dst[1] = __floats2half2_rn(f0.z, f0.w);
    dst[2] = __floats2half2_rn(f1.x, f1.y);
    dst[3] = __floats2half2_rn(f1.z, f1.w);
}

// ---------------- GEMM: transformed = A @ Kh  (split-K into g_partial) ----------------
// grid (NTILES, KSPLIT) = (8,32) = 256 CTAs, 256 threads. M=64, N=128 per CTA, K-chunk 992.
__global__ __launch_bounds__(256) void gemm_step_kernel() {
    const int ntile = blockIdx.x;
    const int ks = blockIdx.y;
    const int tid = threadIdx.x;
    const int wid = tid >> 5, lane = tid & 31;
    const int wm = wid & 1, wn = wid >> 1;   // 2 x 4 warp grid, 32x32 per warp

    __shared__ __half As[STAGES][64 * 40];   // 32 used cols, stride 40 (conflict-free)
    __shared__ __half Bs[STAGES][32 * 136];  // 128 used cols, stride 136 (conflict-free)

    float c[2][4][4];
    #pragma unroll
    for (int i = 0; i < 2; i++)
        #pragma unroll
        for (int j = 0; j < 4; j++)
            #pragma unroll
            for (int q = 0; q < 4; q++) c[i][j][q] = 0.0f;

    const int k0 = ks * KCH;
    const int nbase = ntile * BN;

    // tile loaders
    const int arow = tid >> 2, ach = tid & 3;          // A: 64 rows x 4 chunks
    const int brow = tid >> 4, bch = tid & 15;         // B: 16 rows x 16 chunks (x2)

    #define LOAD_TILES(buf, kg) do {                                            \
        cp_async16(smem_u32(&As[buf][arow * 40 + ach * 8]),                     \
                   g_A + (size_t)arow * KTOT + (kg) + ach * 8);                 \
        cp_async16(smem_u32(&Bs[buf][brow * 136 + bch * 8]),                    \
                   g_Kh + (size_t)((kg) + brow) * ND + nbase + bch * 8);        \
        cp_async16(smem_u32(&Bs[buf][(brow + 16) * 136 + bch * 8]),             \
                   g_Kh + (size_t)((kg) + brow + 16) * ND + nbase + bch * 8);   \
    } while (0)

    LOAD_TILES(0, k0);
    cp_commit();
    LOAD_TILES(1, k0 + BK);
    cp_commit();

    for (int it = 0; it < NIT; ++it) {
        const int buf = it % STAGES;
        cp_wait1();          // stage `it` resident (all but newest group done)
        __syncthreads();

        // issue load for stage it+2 (into the buffer freed at end of it-1)
        if (it + 2 < NIT) {
            LOAD_TILES((it + 2) % STAGES, k0 + (it + 2) * BK);
        }
        cp_commit();         // always commit (possibly empty) to keep group count uniform

        #pragma unroll
        for (int kh = 0; kh < 2; ++kh) {
            uint32_t a[2][4];
            #pragma unroll
            for (int mf = 0; mf < 2; ++mf) {
                uint32_t addr = smem_u32(
                    &As[buf][(wm * 32 + mf * 16 + (lane & 15)) * 40 + kh * 16 + (lane >> 4) * 8]);
                ldm_x4(a[mf], addr);
            }
            uint32_t bb[2][4];
            #pragma unroll
            for (int np = 0; np < 2; ++np) {
                uint32_t addr = smem_u32(
                    &Bs[buf][(kh * 16 + (lane & 15)) * 136 + wn * 32 + np * 16 + (lane >> 4) * 8]);
                ldm_x4t(bb[np], addr);
            }
            #pragma unroll
            for (int mf = 0; mf < 2; ++mf)
                #pragma unroll
                for (int nf = 0; nf < 4; ++nf)
                    mma16816(c[mf][nf], a[mf], bb[nf >> 1][(nf & 1) * 2], bb[nf >> 1][(nf & 1) * 2 + 1]);
        }
        __syncthreads();
    }

    // epilogue: write this split's partial
    float* pp = g_partial + ((size_t)ks * NB * ND);
    #pragma unroll
    for (int mf = 0; mf < 2; ++mf) {
        #pragma unroll
        for (int nf = 0; nf < 4; ++nf) {
            int m = wm * 32 + mf * 16 + (lane >> 2);
            int n = nbase + wn * 32 + nf * 8 + (lane & 3) * 2;
            pp[(size_t)m * ND + n]           = c[mf][nf][0];
            pp[(size_t)m * ND + n + 1]       = c[mf][nf][1];
            pp[(size_t)(m + 8) * ND + n]     = c[mf][nf][2];
            pp[(size_t)(m + 8) * ND + n + 1] = c[mf][nf][3];
        }
    }
}

// ---------------- update: reduce partials, gate, build next A ----------------
// grid (NB, 4) x 256 threads. t = -1: init. t = 15: final (write d_out).
__global__ void update_kernel(const float* __restrict__ signal,
                              float* __restrict__ out, int t) {
    const int b = blockIdx.x;
    const int d = blockIdx.y * 256 + threadIdx.x;
    const bool last = (t == NS - 1);

    __shared__ float wsh[NO];
    if (!last && threadIdx.x < NO) wsh[threadIdx.x] = g_w[t + 1][b][threadIdx.x];

    float hn;
    if (t < 0) {
        hn = signal[b * ND + d];
    } else {
        float tr = 0.0f;
        #pragma unroll
        for (int ks = 0; ks < KSPLIT; ++ks)
            tr += g_partial[(size_t)ks * NB * ND + b * ND + d];
        float g = g_gate[t][b];
        float h = g_h[b * ND + d];
        hn = g * tr + (1.0f - g) * h;
    }
    __syncthreads();

    if (last) {
        out[b * ND + d] = hn;
    } else {
        g_h[b * ND + d] = hn;
        #pragma unroll
        for (int o = 0; o < NO; ++o)
            g_A[(size_t)b * KTOT + o * ND + d] = __float2half(wsh[o] * hn);
    }
}

// ---------------- launch ----------------
extern "C" void kernel_launch(void* const* d_in, const int* in_sizes, int n_in,
                              void* d_out, int out_size) {
    const float* logits   = (const float*)d_in[0];  // (64,16,31)
    const float* operands = (const float*)d_in[1];  // (64,16,4)
    const float* signal   = (const float*)d_in[2];  // (64,1024)
    const float* opk      = (const float*)d_in[3];  // (31,1024,1024)
    float* out = (float*)d_out;                     // (64,1024)

    prep_kernel<<<NB * NS, 32>>>(logits, operands);
    convert_kernel<<<(KTOT * ND) / 8 / 256, 256>>>(opk);
    update_kernel<<<dim3(NB, 4), 256>>>(signal, out, -1);   // init h + A for step 0

    for (int t = 0; t < NS; ++t) {
        gemm_step_kernel<<<dim3(NTILES, KSPLIT), 256>>>();
        update_kernel<<<dim3(NB, 4), 256>>>(signal, out, t);
    }
}